// round 8
// baseline (speedup 1.0000x reference)
#include <cuda_runtime.h>
#include <cuda_fp16.h>

#define H    2048
#define D    2048
#define L    256
#define G3   (3*H)
#define GRID 148
#define THREADS 224
#define NWARP   7
#define UMAX    14
#define NB14    124          // 124*14 + 24*13 = 2048

// ---- device globals (no allocations allowed) ----
__device__ float    g_u[G3], g_v[G3], g_c[G3];  // folded input-path coefficients
__device__ float    g_pred[L];                  // per-step prediction accumulators
__device__ float    g_h[2][H];                  // double-buffered hidden state
__device__ unsigned g_bar;                      // monotonic arrival counter (block0-only reader)
__device__ unsigned long long g_go;             // release packet {stamp, pred}

// ---- smem layout (bytes) ----
#define W_SM_BYTES (UMAX*3*H*2)            // 172032: fp16 W_hh slice [unit*3+gate][k]
#define H_SM_OFF   W_SM_BYTES              // 8192:   h as float[2048]
#define C_SM_OFF   (H_SM_OFF + H*4)
#define SMEM_BYTES (C_SM_OFF + 1024)

__device__ __forceinline__ unsigned ldacq_u32(const unsigned* p) {
    unsigned v;
    asm volatile("ld.acquire.gpu.global.u32 %0, [%1];" : "=r"(v) : "l"(p) : "memory");
    return v;
}
__device__ __forceinline__ float ldacq_f32(const float* p) {
    float v;
    asm volatile("ld.acquire.gpu.global.f32 %0, [%1];" : "=f"(v) : "l"(p) : "memory");
    return v;
}
__device__ __forceinline__ unsigned long long ldacq_u64(const unsigned long long* p) {
    unsigned long long v;
    asm volatile("ld.acquire.gpu.global.u64 %0, [%1];" : "=l"(v) : "l"(p) : "memory");
    return v;
}
__device__ __forceinline__ void strel_u64(unsigned long long* p, unsigned long long v) {
    asm volatile("st.release.gpu.global.u64 [%0], %1;" :: "l"(p), "l"(v) : "memory");
}

// ---------------------------------------------------------------------------
// prep_fused: per-block computes p0/p1/pc in smem, folds W_ih into u/v/c.
// Block 0 resets g_pred/g_bar/g_go (REQUIRED every graph replay), writes out[0].
// x7 = [pk, tp, dose, emb0, emb1, emb2, route]
// ---------------------------------------------------------------------------
__global__ void prep_fused(const float* __restrict__ W_pre, const float* __restrict__ b_pre,
                           const float* __restrict__ dose,  const float* __restrict__ route,
                           const int*   __restrict__ pat_,  const float* __restrict__ emb_table,
                           const float* __restrict__ W_ih,  const float* __restrict__ b_ih,
                           const float* __restrict__ b_hh,  const float* __restrict__ pk_data,
                           float* __restrict__ out)
{
    __shared__ float p0[D], p1[D], pc[D];
    const int tid = threadIdx.x;
    const int pat = pat_[0];
    const float ds = dose[0], rt = route[0];
    const float e0 = emb_table[pat*3+0], e1 = emb_table[pat*3+1], e2 = emb_table[pat*3+2];
    for (int d = tid; d < D; d += 256) {
        const float* w = W_pre + d*7;
        p0[d] = w[0];
        p1[d] = w[1];
        pc[d] = ds*w[2] + e0*w[3] + e1*w[4] + e2*w[5] + rt*w[6] + b_pre[d];
    }
    if (blockIdx.x == 0) {
        if (tid < L)   g_pred[tid] = 0.f;      // L == 256 == blockDim -> full cover
        if (tid == 0) { g_bar = 0u; g_go = 0ull; out[0] = pk_data[0]; }
    }
    __syncthreads();

    const int w = tid >> 5, lane = tid & 31;
    const int g = blockIdx.x * 8 + w;
    const float4* wr = (const float4*)(W_ih + (size_t)g * D);
    const float4* a4 = (const float4*)p0;
    const float4* b4 = (const float4*)p1;
    const float4* c4 = (const float4*)pc;
    float au = 0.f, av = 0.f, ac = 0.f;
    for (int i = lane; i < D/4; i += 32) {
        float4 wv = wr[i], A = a4[i], B = b4[i], C = c4[i];
        au += wv.x*A.x + wv.y*A.y + wv.z*A.z + wv.w*A.w;
        av += wv.x*B.x + wv.y*B.y + wv.z*B.z + wv.w*B.w;
        ac += wv.x*C.x + wv.y*C.y + wv.z*C.z + wv.w*C.w;
    }
    #pragma unroll
    for (int o = 16; o; o >>= 1) {
        au += __shfl_down_sync(0xffffffffu, au, o);
        av += __shfl_down_sync(0xffffffffu, av, o);
        ac += __shfl_down_sync(0xffffffffu, ac, o);
    }
    if (lane == 0) {
        g_u[g] = au; g_v[g] = av;
        float cc = ac + b_ih[g];
        if (g < 2*H) cc += b_hh[g];     // b_hh folds into r,z pre-activations only
        g_c[g] = cc;
    }
}

// ---------------------------------------------------------------------------
// Persistent GRU scan. Compute path VERBATIM from the passing R1/R6 kernel.
// Barrier: R1 arrival (RED pred, fence, RED bar) + new wait side:
//   block0 solely polls g_bar (acquire), publishes {stamp,pred} via release;
//   other blocks acquire-poll the packet (monotonic stamp test).
// ---------------------------------------------------------------------------
__global__ void __launch_bounds__(THREADS, 1)
gru_kernel(const float* __restrict__ W_hh, const float* __restrict__ b_hh,
           const float* __restrict__ W_out, const float* __restrict__ b_out,
           const float* __restrict__ smiles, const float* __restrict__ pk_data,
           const float* __restrict__ timepoints, const int* __restrict__ tf_mask,
           float* __restrict__ out)
{
    extern __shared__ char smem_raw[];
    half*  w_sm  = (half*)smem_raw;                  // [42][2048] fp16
    float* h_sm  = (float*)(smem_raw + H_SM_OFF);    // [2048]
    float* cbase = (float*)(smem_raw + C_SM_OFF);
    float* cu    = cbase;                 // [42] pk coefficient
    float* cv    = cu + 3*UMAX;           // [42] tp coefficient
    float* cc    = cv + 3*UMAX;           // [42] constant (incl biases)
    float* bhn   = cc + 3*UMAX;           // [14] b_hh n-row (multiplied by r)
    float* wo    = bhn + UMAX;            // [14] W_out slice
    float* ppart = wo + UMAX;             // [7]  per-warp pred partials
    float* s_sc  = ppart + NWARP;         // [2]  pk, tp broadcast

    const int tid  = threadIdx.x;
    const int lane = tid & 31;
    const int w    = tid >> 5;
    const int b    = blockIdx.x;
    const int ustart = (b < NB14) ? 14*b : 14*NB14 + 13*(b - NB14);
    const int upb    = (b < NB14) ? 14 : 13;

    // ---- prologue: load W_hh slice fp32->fp16 into smem ----
    const int nrow = 3*upb;
    for (int i = tid; i < nrow*(H/4); i += THREADS) {
        int lr = i >> 9;                 // local row (unit*3 + gate)
        int k4 = i & 511;
        int lu = lr / 3, gate = lr - 3*lu;
        int grow = gate*H + ustart + lu;
        float4 v = *(const float4*)(W_hh + (size_t)grow*H + k4*4);
        *(half2*)(w_sm + lr*H + k4*4)     = __floats2half2_rn(v.x, v.y);
        *(half2*)(w_sm + lr*H + k4*4 + 2) = __floats2half2_rn(v.z, v.w);
    }
    if (upb == 13) {  // zero rows 39..41 so guard-free hot loop is harmless
        for (int i = tid; i < 3*H; i += THREADS) w_sm[39*H + i] = __float2half(0.f);
    }
    for (int j = tid; j < upb*3; j += THREADS) {
        int lu = j/3, gate = j - 3*lu;
        int grow = gate*H + ustart + lu;
        cu[j] = g_u[grow]; cv[j] = g_v[grow]; cc[j] = g_c[grow];
    }
    for (int j = tid; j < upb; j += THREADS) {
        bhn[j] = b_hh[2*H + ustart + j];
        wo[j]  = W_out[ustart + j];
    }
    const float bo = b_out[0];
    if (tid == 0) { s_sc[0] = pk_data[0]; s_sc[1] = timepoints[0]; }

    const int u0 = 2*w;                         // local units u0, u0+1
    int nu = upb - u0; nu = nu < 0 ? 0 : (nu > 2 ? 2 : nu);
    const half* wb = w_sm + (u0*3)*H;

    for (int t = 0; t < L-1; ++t) {
        // stage h_t into smem; MUST bypass L1 (persists across steps within launch)
        const float4* hsrc = (const float4*)((t == 0) ? smiles : g_h[(t-1)&1]);
        float4* hd = (float4*)h_sm;
        for (int i = tid; i < H/4; i += THREADS) hd[i] = __ldcg(hsrc + i);

        // prefetch next-step scalars (read-only inputs, any cache fine)
        int tfn = 0; float pkteach = 0.f, tpn = 0.f;
        if (tid == 0) {
            tfn = __ldg(&tf_mask[t+1]); pkteach = __ldg(&pk_data[t+1]); tpn = __ldg(&timepoints[t+1]);
        }
        __syncthreads();
        const float pk = s_sc[0], tp = s_sc[1];

        // 6 dot products (2 units x 3 gates) over k=0..2047, fp16 weights, fp32 acc
        float acc[6] = {0.f,0.f,0.f,0.f,0.f,0.f};
        #pragma unroll
        for (int ck = 0; ck < 8; ++ck) {
            const int k0 = ck*256 + lane*8;
            const float4 ha = *(const float4*)(h_sm + k0);
            const float4 hb = *(const float4*)(h_sm + k0 + 4);
            #pragma unroll
            for (int r = 0; r < 6; ++r) {
                const uint4 wv = *(const uint4*)(wb + r*H + k0);
                float2 f0 = __half22float2(*(const half2*)&wv.x);
                float2 f1 = __half22float2(*(const half2*)&wv.y);
                float2 f2 = __half22float2(*(const half2*)&wv.z);
                float2 f3 = __half22float2(*(const half2*)&wv.w);
                acc[r] = fmaf(f0.x, ha.x, acc[r]); acc[r] = fmaf(f0.y, ha.y, acc[r]);
                acc[r] = fmaf(f1.x, ha.z, acc[r]); acc[r] = fmaf(f1.y, ha.w, acc[r]);
                acc[r] = fmaf(f2.x, hb.x, acc[r]); acc[r] = fmaf(f2.y, hb.y, acc[r]);
                acc[r] = fmaf(f3.x, hb.z, acc[r]); acc[r] = fmaf(f3.y, hb.w, acc[r]);
            }
        }
        #pragma unroll
        for (int o = 16; o; o >>= 1) {
            #pragma unroll
            for (int r = 0; r < 6; ++r)
                acc[r] += __shfl_down_sync(0xffffffffu, acc[r], o);
        }

        // gate math + h update (lane 0 of each warp, its 1-2 units)
        if (lane == 0) {
            float pp = 0.f;
            #pragma unroll
            for (int un = 0; un < 2; ++un) {
                if (un < nu) {
                    const int j = u0 + un, cb = j*3;
                    const float dr = acc[un*3], dz = acc[un*3+1], dn = acc[un*3+2];
                    const float ar = fmaf(pk, cu[cb],   fmaf(tp, cv[cb],   cc[cb]))   + dr;
                    const float az = fmaf(pk, cu[cb+1], fmaf(tp, cv[cb+1], cc[cb+1])) + dz;
                    const float r  = 1.f/(1.f + __expf(-ar));
                    const float z  = 1.f/(1.f + __expf(-az));
                    const float an = fmaf(pk, cu[cb+2], fmaf(tp, cv[cb+2], cc[cb+2]))
                                   + r*(dn + bhn[j]);
                    const float n  = tanhf(an);
                    const float hnew = fmaf(1.f - z, n, z * h_sm[ustart + j]);
                    g_h[t&1][ustart + j] = hnew;
                    pp += wo[j]*hnew;
                }
            }
            ppart[w] = pp;
            __threadfence();   // publish this warp's h stores before the arrival RED
        }
        __syncthreads();

        // arrival (R1-proven): RED pred, fence, RED bar — then two-stage wait
        if (tid == 0) {
            float s = 0.f;
            #pragma unroll
            for (int i = 0; i < NWARP; ++i) s += ppart[i];
            atomicAdd(&g_pred[t], s);
            __threadfence();                          // order pred add before bar add
            atomicAdd(&g_bar, 1u);                    // result unused -> RED

            float pred;
            if (b == 0) {
                const unsigned target = (unsigned)GRID * (unsigned)(t+1);
                while (ldacq_u32(&g_bar) < target) { }
                pred = ldacq_f32(&g_pred[t]) + bo;
                out[t+1] = pred;
                strel_u64(&g_go, ((unsigned long long)(unsigned)(t+1) << 32) |
                                 (unsigned long long)__float_as_uint(pred));
            } else {
                unsigned long long pkt;
                do { pkt = ldacq_u64(&g_go); }
                while ((unsigned)(pkt >> 32) < (unsigned)(t+1));
                // circularity: stamp cannot pass t+1 until THIS block arrives at t+2,
                // so the observed packet is exactly step t's.
                pred = __uint_as_float((unsigned)pkt);
            }
            s_sc[0] = (tfn == 1) ? pred : pkteach;    // teacher forcing select
            s_sc[1] = tpn;
        }
        __syncthreads();
    }
}

// ---------------------------------------------------------------------------
// Inputs: 0 timepoints, 1 pk_data, 2 input_len, 3 emb_patient, 4 drug_route,
// 5 dose, 6 smiles, 7 tf_mask, 8 emb_table, 9 W_pre, 10 b_pre, 11 W_ih,
// 12 W_hh, 13 b_ih, 14 b_hh, 15 W_out, 16 b_out
// ---------------------------------------------------------------------------
extern "C" void kernel_launch(void* const* d_in, const int* in_sizes, int n_in,
                              void* d_out, int out_size)
{
    const float* timepoints = (const float*)d_in[0];
    const float* pk_data    = (const float*)d_in[1];
    const int*   pat        = (const int*)  d_in[3];
    const float* route      = (const float*)d_in[4];
    const float* dose       = (const float*)d_in[5];
    const float* smiles     = (const float*)d_in[6];
    const int*   tf_mask    = (const int*)  d_in[7];
    const float* emb_table  = (const float*)d_in[8];
    const float* W_pre      = (const float*)d_in[9];
    const float* b_pre      = (const float*)d_in[10];
    const float* W_ih       = (const float*)d_in[11];
    const float* W_hh       = (const float*)d_in[12];
    const float* b_ih       = (const float*)d_in[13];
    const float* b_hh       = (const float*)d_in[14];
    const float* W_out      = (const float*)d_in[15];
    const float* b_out      = (const float*)d_in[16];
    float* out = (float*)d_out;

    cudaFuncSetAttribute(gru_kernel, cudaFuncAttributeMaxDynamicSharedMemorySize, SMEM_BYTES);

    prep_fused<<<G3/8, 256>>>(W_pre, b_pre, dose, route, pat, emb_table,
                              W_ih, b_ih, b_hh, pk_data, out);
    gru_kernel<<<GRID, THREADS, SMEM_BYTES>>>(W_hh, b_hh, W_out, b_out, smiles,
                                              pk_data, timepoints, tf_mask, out);
}

// round 10
// speedup vs baseline: 1.2297x; 1.2297x over previous
#include <cuda_runtime.h>
#include <cuda_fp16.h>

#define H    2048
#define D    2048
#define L    256
#define G3   (3*H)
#define GRID 148
#define THREADS 224
#define NWARP   7
#define UMAX    14
#define NB14    124          // 124*14 + 24*13 = 2048

// ---- device globals (no allocations allowed) ----
__device__ float    g_u[G3], g_v[G3], g_c[G3];  // folded input-path coefficients
__device__ float    g_h[2][H];                  // double-buffered hidden state
__device__ unsigned g_bar;                      // monotonic arrival counter

// ---- smem layout (bytes) ----
#define W_SM_BYTES   (UMAX*3*H*2)          // 172032: fp16 W_hh slice
#define H_SM_OFF     W_SM_BYTES            // 8192:   h as float[2048]
#define WO_SM_OFF    (H_SM_OFF + H*4)      // 8192:   full W_out
#define TP_SM_OFF    (WO_SM_OFF + H*4)     // 1024:   timepoints
#define PKD_SM_OFF   (TP_SM_OFF + L*4)     // 1024:   pk_data
#define TF_SM_OFF    (PKD_SM_OFF + L*4)    // 1024:   tf_mask
#define C_SM_OFF     (TF_SM_OFF + L*4)     // small constants
#define SMEM_BYTES   (C_SM_OFF + 1024)

// ---------------------------------------------------------------------------
// prep_fused: per-block computes p0/p1/pc in smem, folds W_ih into u/v/c.
// Block 0 resets g_bar (REQUIRED every graph replay) and writes out[0].
// x7 = [pk, tp, dose, emb0, emb1, emb2, route]
// ---------------------------------------------------------------------------
__global__ void prep_fused(const float* __restrict__ W_pre, const float* __restrict__ b_pre,
                           const float* __restrict__ dose,  const float* __restrict__ route,
                           const int*   __restrict__ pat_,  const float* __restrict__ emb_table,
                           const float* __restrict__ W_ih,  const float* __restrict__ b_ih,
                           const float* __restrict__ b_hh,  const float* __restrict__ pk_data,
                           float* __restrict__ out)
{
    __shared__ float p0[D], p1[D], pc[D];
    const int tid = threadIdx.x;
    const int pat = pat_[0];
    const float ds = dose[0], rt = route[0];
    const float e0 = emb_table[pat*3+0], e1 = emb_table[pat*3+1], e2 = emb_table[pat*3+2];
    for (int d = tid; d < D; d += 256) {
        const float* w = W_pre + d*7;
        p0[d] = w[0];
        p1[d] = w[1];
        pc[d] = ds*w[2] + e0*w[3] + e1*w[4] + e2*w[5] + rt*w[6] + b_pre[d];
    }
    if (blockIdx.x == 0 && tid == 0) { g_bar = 0u; out[0] = pk_data[0]; }
    __syncthreads();

    const int w = tid >> 5, lane = tid & 31;
    const int g = blockIdx.x * 8 + w;
    const float4* wr = (const float4*)(W_ih + (size_t)g * D);
    const float4* a4 = (const float4*)p0;
    const float4* b4 = (const float4*)p1;
    const float4* c4 = (const float4*)pc;
    float au = 0.f, av = 0.f, ac = 0.f;
    for (int i = lane; i < D/4; i += 32) {
        float4 wv = wr[i], A = a4[i], B = b4[i], C = c4[i];
        au += wv.x*A.x + wv.y*A.y + wv.z*A.z + wv.w*A.w;
        av += wv.x*B.x + wv.y*B.y + wv.z*B.z + wv.w*B.w;
        ac += wv.x*C.x + wv.y*C.y + wv.z*C.z + wv.w*C.w;
    }
    #pragma unroll
    for (int o = 16; o; o >>= 1) {
        au += __shfl_down_sync(0xffffffffu, au, o);
        av += __shfl_down_sync(0xffffffffu, av, o);
        ac += __shfl_down_sync(0xffffffffu, ac, o);
    }
    if (lane == 0) {
        g_u[g] = au; g_v[g] = av;
        float cc = ac + b_ih[g];
        if (g < 2*H) cc += b_hh[g];     // b_hh folds into r,z pre-activations only
        g_c[g] = cc;
    }
}

// ---------------------------------------------------------------------------
// Persistent GRU scan. Compute loop VERBATIM from the passing R1/R6 kernel.
// pred is computed REDUNDANTLY per block from the staged h (no g_pred atomic);
// barrier = R6-proven minimal form: fence -> RED g_bar -> tid0 spin -> fence.
// ---------------------------------------------------------------------------
__global__ void __launch_bounds__(THREADS, 1)
gru_kernel(const float* __restrict__ W_hh, const float* __restrict__ b_hh,
           const float* __restrict__ W_out, const float* __restrict__ b_out,
           const float* __restrict__ smiles, const float* __restrict__ pk_data,
           const float* __restrict__ timepoints, const int* __restrict__ tf_mask,
           float* __restrict__ out)
{
    extern __shared__ char smem_raw[];
    half*  w_sm   = (half*)smem_raw;                   // [42][2048] fp16
    float* h_sm   = (float*)(smem_raw + H_SM_OFF);     // [2048]
    float* wo_sm  = (float*)(smem_raw + WO_SM_OFF);    // [2048] full W_out
    float* tp_sm  = (float*)(smem_raw + TP_SM_OFF);    // [256]
    float* pkd_sm = (float*)(smem_raw + PKD_SM_OFF);   // [256]
    int*   tf_sm  = (int*)  (smem_raw + TF_SM_OFF);    // [256]
    float* cbase  = (float*)(smem_raw + C_SM_OFF);
    float* cu    = cbase;                 // [42] pk coefficient
    float* cv    = cu + 3*UMAX;           // [42] tp coefficient
    float* cc    = cv + 3*UMAX;           // [42] constant (incl biases)
    float* bhn   = cc + 3*UMAX;           // [14] b_hh n-row (multiplied by r)
    float* ppart = bhn + UMAX;            // [7]  per-warp pred partials

    const int tid  = threadIdx.x;
    const int lane = tid & 31;
    const int w    = tid >> 5;
    const int b    = blockIdx.x;
    const int ustart = (b < NB14) ? 14*b : 14*NB14 + 13*(b - NB14);
    const int upb    = (b < NB14) ? 14 : 13;

    // ---- prologue: load W_hh slice fp32->fp16 into smem ----
    const int nrow = 3*upb;
    for (int i = tid; i < nrow*(H/4); i += THREADS) {
        int lr = i >> 9;                 // local row (unit*3 + gate)
        int k4 = i & 511;
        int lu = lr / 3, gate = lr - 3*lu;
        int grow = gate*H + ustart + lu;
        float4 v = *(const float4*)(W_hh + (size_t)grow*H + k4*4);
        *(half2*)(w_sm + lr*H + k4*4)     = __floats2half2_rn(v.x, v.y);
        *(half2*)(w_sm + lr*H + k4*4 + 2) = __floats2half2_rn(v.z, v.w);
    }
    if (upb == 13) {  // zero rows 39..41 so guard-free hot loop is harmless
        for (int i = tid; i < 3*H; i += THREADS) w_sm[39*H + i] = __float2half(0.f);
    }
    for (int j = tid; j < upb*3; j += THREADS) {
        int lu = j/3, gate = j - 3*lu;
        int grow = gate*H + ustart + lu;
        cu[j] = g_u[grow]; cv[j] = g_v[grow]; cc[j] = g_c[grow];
    }
    for (int j = tid; j < upb; j += THREADS) bhn[j] = b_hh[2*H + ustart + j];
    // full W_out + per-step scalars into smem (kills per-step global loads)
    for (int k = tid; k < H; k += THREADS) wo_sm[k] = W_out[k];
    for (int k = tid; k < L; k += THREADS) {
        tp_sm[k]  = timepoints[k];
        pkd_sm[k] = pk_data[k];
        tf_sm[k]  = tf_mask[k];
    }
    const float bo = b_out[0];

    const int u0 = 2*w;                         // local units u0, u0+1
    int nu = upb - u0; nu = nu < 0 ? 0 : (nu > 2 ? 2 : nu);
    const half* wb = w_sm + (u0*3)*H;
    __syncthreads();

    for (int t = 0; t < L-1; ++t) {
        // A: stage h_{t-1} into smem; MUST bypass L1 (stale across steps)
        const float4* hsrc = (const float4*)((t == 0) ? smiles : g_h[(t-1)&1]);
        float4* hd = (float4*)h_sm;
        for (int i = tid; i < H/4; i += THREADS) hd[i] = __ldcg(hsrc + i);
        __syncthreads();                                   // h_sm ready

        // B: redundant block-local pred_{t-1} = W_out . h_{t-1} + bo  (t>=1)
        float pk, tp = tp_sm[t];
        if (t > 0) {
            float s = 0.f;
            for (int k = tid; k < H; k += THREADS) s = fmaf(wo_sm[k], h_sm[k], s);
            #pragma unroll
            for (int o = 16; o; o >>= 1) s += __shfl_down_sync(0xffffffffu, s, o);
            if (lane == 0) ppart[w] = s;
            __syncthreads();                               // partials ready
            const float pred = ((ppart[0]+ppart[1])+(ppart[2]+ppart[3]))
                             + ((ppart[4]+ppart[5])+ppart[6]) + bo;   // identical in all threads/blocks
            if (b == 0 && tid == 0) out[t] = pred;
            pk = (tf_sm[t] == 1) ? pred : pkd_sm[t];
        } else {
            pk = pkd_sm[0];
        }

        // C: 6 dot products (2 units x 3 gates), fp16 weights, fp32 acc (frozen)
        float acc[6] = {0.f,0.f,0.f,0.f,0.f,0.f};
        #pragma unroll
        for (int ck = 0; ck < 8; ++ck) {
            const int k0 = ck*256 + lane*8;
            const float4 ha = *(const float4*)(h_sm + k0);
            const float4 hb = *(const float4*)(h_sm + k0 + 4);
            #pragma unroll
            for (int r = 0; r < 6; ++r) {
                const uint4 wv = *(const uint4*)(wb + r*H + k0);
                float2 f0 = __half22float2(*(const half2*)&wv.x);
                float2 f1 = __half22float2(*(const half2*)&wv.y);
                float2 f2 = __half22float2(*(const half2*)&wv.z);
                float2 f3 = __half22float2(*(const half2*)&wv.w);
                acc[r] = fmaf(f0.x, ha.x, acc[r]); acc[r] = fmaf(f0.y, ha.y, acc[r]);
                acc[r] = fmaf(f1.x, ha.z, acc[r]); acc[r] = fmaf(f1.y, ha.w, acc[r]);
                acc[r] = fmaf(f2.x, hb.x, acc[r]); acc[r] = fmaf(f2.y, hb.y, acc[r]);
                acc[r] = fmaf(f3.x, hb.z, acc[r]); acc[r] = fmaf(f3.y, hb.w, acc[r]);
            }
        }
        #pragma unroll
        for (int o = 16; o; o >>= 1) {
            #pragma unroll
            for (int r = 0; r < 6; ++r)
                acc[r] += __shfl_down_sync(0xffffffffu, acc[r], o);
        }

        // D: gate math + h update (lane 0 of each warp, its 1-2 units)
        if (lane == 0) {
            #pragma unroll
            for (int un = 0; un < 2; ++un) {
                if (un < nu) {
                    const int j = u0 + un, cb = j*3;
                    const float dr = acc[un*3], dz = acc[un*3+1], dn = acc[un*3+2];
                    const float ar = fmaf(pk, cu[cb],   fmaf(tp, cv[cb],   cc[cb]))   + dr;
                    const float az = fmaf(pk, cu[cb+1], fmaf(tp, cv[cb+1], cc[cb+1])) + dz;
                    const float r  = 1.f/(1.f + __expf(-ar));
                    const float z  = 1.f/(1.f + __expf(-az));
                    const float an = fmaf(pk, cu[cb+2], fmaf(tp, cv[cb+2], cc[cb+2]))
                                   + r*(dn + bhn[j]);
                    const float n  = tanhf(an);
                    const float hnew = fmaf(1.f - z, n, z * h_sm[ustart + j]);
                    g_h[t&1][ustart + j] = hnew;
                }
            }
        }
        __syncthreads();                                   // all h stores issued

        // E: minimal grid barrier (R1/R6-proven pattern)
        if (tid == 0) {
            __threadfence();                               // release h stores
            atomicAdd(&g_bar, 1u);                         // RED (result unused)
            const unsigned target = (unsigned)GRID * (unsigned)(t+1);
            volatile unsigned* vb = &g_bar;
            while (*vb < target) { }
            __threadfence();                               // acquire others' h
        }
        __syncthreads();
    }

    // epilogue: out[255] = W_out . h_254 + bo  (block 0 only; h visible post-barrier)
    if (b == 0) {
        const float4* hsrc = (const float4*)g_h[(L-2)&1];  // t=254 -> buffer 0
        float4* hd = (float4*)h_sm;
        for (int i = tid; i < H/4; i += THREADS) hd[i] = __ldcg(hsrc + i);
        __syncthreads();
        float s = 0.f;
        for (int k = tid; k < H; k += THREADS) s = fmaf(wo_sm[k], h_sm[k], s);
        #pragma unroll
        for (int o = 16; o; o >>= 1) s += __shfl_down_sync(0xffffffffu, s, o);
        if (lane == 0) ppart[w] = s;
        __syncthreads();
        if (tid == 0)
            out[L-1] = ((ppart[0]+ppart[1])+(ppart[2]+ppart[3]))
                     + ((ppart[4]+ppart[5])+ppart[6]) + bo;
    }
}

// ---------------------------------------------------------------------------
// Inputs: 0 timepoints, 1 pk_data, 2 input_len, 3 emb_patient, 4 drug_route,
// 5 dose, 6 smiles, 7 tf_mask, 8 emb_table, 9 W_pre, 10 b_pre, 11 W_ih,
// 12 W_hh, 13 b_ih, 14 b_hh, 15 W_out, 16 b_out
// ---------------------------------------------------------------------------
extern "C" void kernel_launch(void* const* d_in, const int* in_sizes, int n_in,
                              void* d_out, int out_size)
{
    const float* timepoints = (const float*)d_in[0];
    const float* pk_data    = (const float*)d_in[1];
    const int*   pat        = (const int*)  d_in[3];
    const float* route      = (const float*)d_in[4];
    const float* dose       = (const float*)d_in[5];
    const float* smiles     = (const float*)d_in[6];
    const int*   tf_mask    = (const int*)  d_in[7];
    const float* emb_table  = (const float*)d_in[8];
    const float* W_pre      = (const float*)d_in[9];
    const float* b_pre      = (const float*)d_in[10];
    const float* W_ih       = (const float*)d_in[11];
    const float* W_hh       = (const float*)d_in[12];
    const float* b_ih       = (const float*)d_in[13];
    const float* b_hh       = (const float*)d_in[14];
    const float* W_out      = (const float*)d_in[15];
    const float* b_out      = (const float*)d_in[16];
    float* out = (float*)d_out;

    cudaFuncSetAttribute(gru_kernel, cudaFuncAttributeMaxDynamicSharedMemorySize, SMEM_BYTES);

    prep_fused<<<G3/8, 256>>>(W_pre, b_pre, dose, route, pat, emb_table,
                              W_ih, b_ih, b_hh, pk_data, out);
    gru_kernel<<<GRID, THREADS, SMEM_BYTES>>>(W_hh, b_hh, W_out, b_out, smiles,
                                              pk_data, timepoints, tf_mask, out);
}

// round 13
// speedup vs baseline: 1.4613x; 1.1884x over previous
#include <cuda_runtime.h>
#include <cuda_fp16.h>

#define H    2048
#define D    2048
#define L    256
#define G3   (3*H)
#define GRID 148
#define THREADS 224
#define NWARP   7
#define UMAX    14
#define NB14    124          // 124*14 + 24*13 = 2048

// ---- device globals (no allocations allowed) ----
__device__ float    g_u[G3], g_v[G3], g_c[G3];  // folded input-path coefficients
__device__ float    g_h[2][H];                  // double-buffered hidden state
__device__ unsigned g_bar;                      // monotonic arrival counter

// ---- smem layout (bytes) ----
#define W_SM_BYTES   (UMAX*3*H*2)          // 172032: fp16 W_hh slice
#define H_SM_OFF     W_SM_BYTES            // 8192:   h as float[2048]
#define WO_SM_OFF    (H_SM_OFF + H*4)      // 8192:   full W_out
#define TP_SM_OFF    (WO_SM_OFF + H*4)     // 1024:   timepoints
#define PKD_SM_OFF   (TP_SM_OFF + L*4)     // 1024:   pk_data
#define TF_SM_OFF    (PKD_SM_OFF + L*4)    // 1024:   tf_mask
#define C_SM_OFF     (TF_SM_OFF + L*4)     // small constants
#define SMEM_BYTES   (C_SM_OFF + 1024)

// ---------------------------------------------------------------------------
// prep_fused: per-block computes p0/p1/pc in smem, folds W_ih into u/v/c.
// Block 0 resets g_bar (REQUIRED every graph replay) and writes out[0].
// x7 = [pk, tp, dose, emb0, emb1, emb2, route]
// ---------------------------------------------------------------------------
__global__ void prep_fused(const float* __restrict__ W_pre, const float* __restrict__ b_pre,
                           const float* __restrict__ dose,  const float* __restrict__ route,
                           const int*   __restrict__ pat_,  const float* __restrict__ emb_table,
                           const float* __restrict__ W_ih,  const float* __restrict__ b_ih,
                           const float* __restrict__ b_hh,  const float* __restrict__ pk_data,
                           float* __restrict__ out)
{
    __shared__ float p0[D], p1[D], pc[D];
    const int tid = threadIdx.x;
    const int pat = pat_[0];
    const float ds = dose[0], rt = route[0];
    const float e0 = emb_table[pat*3+0], e1 = emb_table[pat*3+1], e2 = emb_table[pat*3+2];
    for (int d = tid; d < D; d += 256) {
        const float* w = W_pre + d*7;
        p0[d] = w[0];
        p1[d] = w[1];
        pc[d] = ds*w[2] + e0*w[3] + e1*w[4] + e2*w[5] + rt*w[6] + b_pre[d];
    }
    if (blockIdx.x == 0 && tid == 0) { g_bar = 0u; out[0] = pk_data[0]; }
    __syncthreads();

    const int w = tid >> 5, lane = tid & 31;
    const int g = blockIdx.x * 8 + w;
    const float4* wr = (const float4*)(W_ih + (size_t)g * D);
    const float4* a4 = (const float4*)p0;
    const float4* b4 = (const float4*)p1;
    const float4* c4 = (const float4*)pc;
    float au = 0.f, av = 0.f, ac = 0.f;
    for (int i = lane; i < D/4; i += 32) {
        float4 wv = wr[i], A = a4[i], B = b4[i], C = c4[i];
        au += wv.x*A.x + wv.y*A.y + wv.z*A.z + wv.w*A.w;
        av += wv.x*B.x + wv.y*B.y + wv.z*B.z + wv.w*B.w;
        ac += wv.x*C.x + wv.y*C.y + wv.z*C.z + wv.w*C.w;
    }
    #pragma unroll
    for (int o = 16; o; o >>= 1) {
        au += __shfl_down_sync(0xffffffffu, au, o);
        av += __shfl_down_sync(0xffffffffu, av, o);
        ac += __shfl_down_sync(0xffffffffu, ac, o);
    }
    if (lane == 0) {
        g_u[g] = au; g_v[g] = av;
        float cc = ac + b_ih[g];
        if (g < 2*H) cc += b_hh[g];     // b_hh folds into r,z pre-activations only
        g_c[g] = cc;
    }
}

// ---------------------------------------------------------------------------
// Persistent GRU scan. Numerics frozen (fp16 W_hh smem / fp32 h / fp32 acc).
// Step: stage h (+fold pred from staged registers) -> dot -> butterfly reduce
// (sums broadcast to all lanes) -> gates split lane0/lane16 -> proven barrier.
// ---------------------------------------------------------------------------
__global__ void __launch_bounds__(THREADS, 1)
gru_kernel(const float* __restrict__ W_hh, const float* __restrict__ b_hh,
           const float* __restrict__ W_out, const float* __restrict__ b_out,
           const float* __restrict__ smiles, const float* __restrict__ pk_data,
           const float* __restrict__ timepoints, const int* __restrict__ tf_mask,
           float* __restrict__ out)
{
    extern __shared__ char smem_raw[];
    half*  w_sm   = (half*)smem_raw;                   // [42][2048] fp16
    float* h_sm   = (float*)(smem_raw + H_SM_OFF);     // [2048]
    float* wo_sm  = (float*)(smem_raw + WO_SM_OFF);    // [2048] full W_out
    float* tp_sm  = (float*)(smem_raw + TP_SM_OFF);    // [256]
    float* pkd_sm = (float*)(smem_raw + PKD_SM_OFF);   // [256]
    int*   tf_sm  = (int*)  (smem_raw + TF_SM_OFF);    // [256]
    float* cbase  = (float*)(smem_raw + C_SM_OFF);
    float* cu    = cbase;                 // [42] pk coefficient
    float* cv    = cu + 3*UMAX;           // [42] tp coefficient
    float* cc    = cv + 3*UMAX;           // [42] constant (incl biases)
    float* bhn   = cc + 3*UMAX;           // [14] b_hh n-row (multiplied by r)
    float* ppart = bhn + UMAX;            // [7]  per-warp pred partials

    const int tid  = threadIdx.x;
    const int lane = tid & 31;
    const int w    = tid >> 5;
    const int b    = blockIdx.x;
    const int ustart = (b < NB14) ? 14*b : 14*NB14 + 13*(b - NB14);
    const int upb    = (b < NB14) ? 14 : 13;

    // ---- prologue: load W_hh slice fp32->fp16 into smem ----
    const int nrow = 3*upb;
    for (int i = tid; i < nrow*(H/4); i += THREADS) {
        int lr = i >> 9;                 // local row (unit*3 + gate)
        int k4 = i & 511;
        int lu = lr / 3, gate = lr - 3*lu;
        int grow = gate*H + ustart + lu;
        float4 v = *(const float4*)(W_hh + (size_t)grow*H + k4*4);
        *(half2*)(w_sm + lr*H + k4*4)     = __floats2half2_rn(v.x, v.y);
        *(half2*)(w_sm + lr*H + k4*4 + 2) = __floats2half2_rn(v.z, v.w);
    }
    if (upb == 13) {  // zero rows 39..41 so guard-free hot loop is harmless
        for (int i = tid; i < 3*H; i += THREADS) w_sm[39*H + i] = __float2half(0.f);
    }
    for (int j = tid; j < upb*3; j += THREADS) {
        int lu = j/3, gate = j - 3*lu;
        int grow = gate*H + ustart + lu;
        cu[j] = g_u[grow]; cv[j] = g_v[grow]; cc[j] = g_c[grow];
    }
    for (int j = tid; j < upb; j += THREADS) bhn[j] = b_hh[2*H + ustart + j];
    for (int k = tid; k < H; k += THREADS) wo_sm[k] = W_out[k];
    for (int k = tid; k < L; k += THREADS) {
        tp_sm[k]  = timepoints[k];
        pkd_sm[k] = pk_data[k];
        tf_sm[k]  = tf_mask[k];
    }
    const float bo = b_out[0];

    const int u0 = 2*w;                         // local units u0, u0+1
    int nu = upb - u0; nu = nu < 0 ? 0 : (nu > 2 ? 2 : nu);
    const half* wb = w_sm + (u0*3)*H;
    const float4* wo4 = (const float4*)wo_sm;
    __syncthreads();

    for (int t = 0; t < L-1; ++t) {
        // A: stage h_{t-1} (L1-bypass, MLP=3) and fold pred = wo.h from the
        //    SAME registers — the separate pred pass is deleted.
        const float4* hsrc = (const float4*)((t == 0) ? smiles : g_h[(t-1)&1]);
        float4* hd = (float4*)h_sm;
        const float4 v0 = __ldcg(hsrc + tid);
        const float4 v1 = __ldcg(hsrc + tid + 224);
        float4 v2 = make_float4(0.f, 0.f, 0.f, 0.f);
        if (tid < 64) v2 = __ldcg(hsrc + tid + 448);
        hd[tid]       = v0;
        hd[tid + 224] = v1;
        if (tid < 64) hd[tid + 448] = v2;
        {
            const float4 q0 = wo4[tid];
            const float4 q1 = wo4[tid + 224];
            float sp = q0.x*v0.x + q0.y*v0.y + q0.z*v0.z + q0.w*v0.w
                     + q1.x*v1.x + q1.y*v1.y + q1.z*v1.z + q1.w*v1.w;
            if (tid < 64) {
                const float4 q2 = wo4[tid + 448];
                sp += q2.x*v2.x + q2.y*v2.y + q2.z*v2.z + q2.w*v2.w;
            }
            #pragma unroll
            for (int o = 16; o; o >>= 1) sp += __shfl_xor_sync(0xffffffffu, sp, o);
            if (lane == 0) ppart[w] = sp;
        }
        __syncthreads();                                   // h_sm + ppart ready

        const float pred = ((ppart[0]+ppart[1])+(ppart[2]+ppart[3]))
                         + ((ppart[4]+ppart[5])+ppart[6]) + bo;  // identical everywhere
        if (b == 0 && tid == 0 && t > 0) out[t] = pred;
        const float pk = (t > 0 && tf_sm[t] == 1) ? pred : pkd_sm[t];
        const float tp = tp_sm[t];

        // C: 6 dot products (2 units x 3 gates), fp16 weights, fp32 acc (frozen)
        float acc[6] = {0.f,0.f,0.f,0.f,0.f,0.f};
        #pragma unroll
        for (int ck = 0; ck < 8; ++ck) {
            const int k0 = ck*256 + lane*8;
            const float4 ha = *(const float4*)(h_sm + k0);
            const float4 hb = *(const float4*)(h_sm + k0 + 4);
            #pragma unroll
            for (int r = 0; r < 6; ++r) {
                const uint4 wv = *(const uint4*)(wb + r*H + k0);
                float2 f0 = __half22float2(*(const half2*)&wv.x);
                float2 f1 = __half22float2(*(const half2*)&wv.y);
                float2 f2 = __half22float2(*(const half2*)&wv.z);
                float2 f3 = __half22float2(*(const half2*)&wv.w);
                acc[r] = fmaf(f0.x, ha.x, acc[r]); acc[r] = fmaf(f0.y, ha.y, acc[r]);
                acc[r] = fmaf(f1.x, ha.z, acc[r]); acc[r] = fmaf(f1.y, ha.w, acc[r]);
                acc[r] = fmaf(f2.x, hb.x, acc[r]); acc[r] = fmaf(f2.y, hb.y, acc[r]);
                acc[r] = fmaf(f3.x, hb.z, acc[r]); acc[r] = fmaf(f3.y, hb.w, acc[r]);
            }
        }
        // butterfly: every lane ends with all 6 full sums (enables split gates)
        #pragma unroll
        for (int o = 16; o; o >>= 1) {
            #pragma unroll
            for (int r = 0; r < 6; ++r)
                acc[r] += __shfl_xor_sync(0xffffffffu, acc[r], o);
        }

        // D: gate math split across lane0 (unit u0) and lane16 (unit u0+1)
        if ((lane == 0) || (lane == 16 && nu == 2)) {
            const int un = (lane == 0) ? 0 : 1;
            const int j = u0 + un, cb = j*3;
            const float dr = acc[un*3], dz = acc[un*3+1], dn = acc[un*3+2];
            const float ar = fmaf(pk, cu[cb],   fmaf(tp, cv[cb],   cc[cb]))   + dr;
            const float az = fmaf(pk, cu[cb+1], fmaf(tp, cv[cb+1], cc[cb+1])) + dz;
            const float r  = 1.f/(1.f + __expf(-ar));
            const float z  = 1.f/(1.f + __expf(-az));
            const float an = fmaf(pk, cu[cb+2], fmaf(tp, cv[cb+2], cc[cb+2]))
                           + r*(dn + bhn[j]);
            const float n  = tanhf(an);
            const float hnew = fmaf(1.f - z, n, z * h_sm[ustart + j]);
            g_h[t&1][ustart + j] = hnew;
        }
        __syncthreads();                                   // all h stores issued

        // E: minimal grid barrier (R1/R6/R10-proven pattern — frozen)
        if (tid == 0) {
            __threadfence();                               // release h stores
            atomicAdd(&g_bar, 1u);                         // RED (result unused)
            const unsigned target = (unsigned)GRID * (unsigned)(t+1);
            volatile unsigned* vb = &g_bar;
            while (*vb < target) { }
            __threadfence();                               // acquire others' h
        }
        __syncthreads();
    }

    // epilogue: out[255] = W_out . h_final + bo  (block 0 only)
    if (b == 0) {
        const float4* hsrc = (const float4*)g_h[(L-2)&1];
        float4* hd = (float4*)h_sm;
        for (int i = tid; i < H/4; i += THREADS) hd[i] = __ldcg(hsrc + i);
        __syncthreads();
        float s = 0.f;
        for (int k = tid; k < H; k += THREADS) s = fmaf(wo_sm[k], h_sm[k], s);
        #pragma unroll
        for (int o = 16; o; o >>= 1) s += __shfl_xor_sync(0xffffffffu, s, o);
        if (lane == 0) ppart[w] = s;
        __syncthreads();
        if (tid == 0)
            out[L-1] = ((ppart[0]+ppart[1])+(ppart[2]+ppart[3]))
                     + ((ppart[4]+ppart[5])+ppart[6]) + bo;
    }
}

// ---------------------------------------------------------------------------
// Inputs: 0 timepoints, 1 pk_data, 2 input_len, 3 emb_patient, 4 drug_route,
// 5 dose, 6 smiles, 7 tf_mask, 8 emb_table, 9 W_pre, 10 b_pre, 11 W_ih,
// 12 W_hh, 13 b_ih, 14 b_hh, 15 W_out, 16 b_out
// ---------------------------------------------------------------------------
extern "C" void kernel_launch(void* const* d_in, const int* in_sizes, int n_in,
                              void* d_out, int out_size)
{
    const float* timepoints = (const float*)d_in[0];
    const float* pk_data    = (const float*)d_in[1];
    const int*   pat        = (const int*)  d_in[3];
    const float* route      = (const float*)d_in[4];
    const float* dose       = (const float*)d_in[5];
    const float* smiles     = (const float*)d_in[6];
    const int*   tf_mask    = (const int*)  d_in[7];
    const float* emb_table  = (const float*)d_in[8];
    const float* W_pre      = (const float*)d_in[9];
    const float* b_pre      = (const float*)d_in[10];
    const float* W_ih       = (const float*)d_in[11];
    const float* W_hh       = (const float*)d_in[12];
    const float* b_ih       = (const float*)d_in[13];
    const float* b_hh       = (const float*)d_in[14];
    const float* W_out      = (const float*)d_in[15];
    const float* b_out      = (const float*)d_in[16];
    float* out = (float*)d_out;

    cudaFuncSetAttribute(gru_kernel, cudaFuncAttributeMaxDynamicSharedMemorySize, SMEM_BYTES);

    prep_fused<<<G3/8, 256>>>(W_pre, b_pre, dose, route, pat, emb_table,
                              W_ih, b_ih, b_hh, pk_data, out);
    gru_kernel<<<GRID, THREADS, SMEM_BYTES>>>(W_hh, b_hh, W_out, b_out, smiles,
                                              pk_data, timepoints, tf_mask, out);
}

// round 15
// speedup vs baseline: 1.5965x; 1.0925x over previous
#include <cuda_runtime.h>
#include <cuda_fp16.h>

#define H    2048
#define D    2048
#define L    256
#define G3   (3*H)
#define GRID 148
#define THREADS 224
#define NWARP   7
#define UMAX    14
#define NB14    124          // 124*14 + 24*13 = 2048

// ---- device globals (no allocations allowed) ----
__device__ float    g_u[G3], g_v[G3], g_c[G3];  // folded input-path coefficients
__device__ float    g_h[2][H];                  // double-buffered hidden state
__device__ unsigned g_bar;                      // monotonic arrival counter

// ---------------------------------------------------------------------------
// prep_fused: per-block computes p0/p1/pc in smem, folds W_ih into u/v/c.
// Block 0 resets g_bar (REQUIRED every graph replay) and writes out[0].
// x7 = [pk, tp, dose, emb0, emb1, emb2, route]
// ---------------------------------------------------------------------------
__global__ void prep_fused(const float* __restrict__ W_pre, const float* __restrict__ b_pre,
                           const float* __restrict__ dose,  const float* __restrict__ route,
                           const int*   __restrict__ pat_,  const float* __restrict__ emb_table,
                           const float* __restrict__ W_ih,  const float* __restrict__ b_ih,
                           const float* __restrict__ b_hh,  const float* __restrict__ pk_data,
                           float* __restrict__ out)
{
    __shared__ float p0[D], p1[D], pc[D];
    const int tid = threadIdx.x;
    const int pat = pat_[0];
    const float ds = dose[0], rt = route[0];
    const float e0 = emb_table[pat*3+0], e1 = emb_table[pat*3+1], e2 = emb_table[pat*3+2];
    for (int d = tid; d < D; d += 256) {
        const float* w = W_pre + d*7;
        p0[d] = w[0];
        p1[d] = w[1];
        pc[d] = ds*w[2] + e0*w[3] + e1*w[4] + e2*w[5] + rt*w[6] + b_pre[d];
    }
    if (blockIdx.x == 0 && tid == 0) { g_bar = 0u; out[0] = pk_data[0]; }
    __syncthreads();

    const int w = tid >> 5, lane = tid & 31;
    const int g = blockIdx.x * 8 + w;
    const float4* wr = (const float4*)(W_ih + (size_t)g * D);
    const float4* a4 = (const float4*)p0;
    const float4* b4 = (const float4*)p1;
    const float4* c4 = (const float4*)pc;
    float au = 0.f, av = 0.f, ac = 0.f;
    for (int i = lane; i < D/4; i += 32) {
        float4 wv = wr[i], A = a4[i], B = b4[i], C = c4[i];
        au += wv.x*A.x + wv.y*A.y + wv.z*A.z + wv.w*A.w;
        av += wv.x*B.x + wv.y*B.y + wv.z*B.z + wv.w*B.w;
        ac += wv.x*C.x + wv.y*C.y + wv.z*C.z + wv.w*C.w;
    }
    #pragma unroll
    for (int o = 16; o; o >>= 1) {
        au += __shfl_down_sync(0xffffffffu, au, o);
        av += __shfl_down_sync(0xffffffffu, av, o);
        ac += __shfl_down_sync(0xffffffffu, ac, o);
    }
    if (lane == 0) {
        g_u[g] = au; g_v[g] = av;
        float cc = ac + b_ih[g];
        if (g < 2*H) cc += b_hh[g];     // b_hh folds into r,z pre-activations only
        g_c[g] = cc;
    }
}

// ---------------------------------------------------------------------------
// Persistent GRU scan. Numerics frozen (fp16 weights / fp32 h / fp32 acc,
// identical FMA order). NEW: the W_hh slice lives in REGISTERS (192 half2
// per thread), not smem — deletes 48 weight LDS.128/thread/step.
// ---------------------------------------------------------------------------
__global__ void __launch_bounds__(THREADS, 1)
gru_kernel(const float* __restrict__ W_hh, const float* __restrict__ b_hh,
           const float* __restrict__ W_out, const float* __restrict__ b_out,
           const float* __restrict__ smiles, const float* __restrict__ pk_data,
           const float* __restrict__ timepoints, const int* __restrict__ tf_mask,
           float* __restrict__ out)
{
    __shared__ float h_sm[H];            // staged h (fp32)
    __shared__ float wo_sm[H];           // full W_out
    __shared__ float tp_sm[L];
    __shared__ float pkd_sm[L];
    __shared__ int   tf_sm[L];
    __shared__ float cu[3*UMAX], cv[3*UMAX], ccs[3*UMAX];
    __shared__ float bhn[UMAX];
    __shared__ float ppart[NWARP];

    const int tid  = threadIdx.x;
    const int lane = tid & 31;
    const int w    = tid >> 5;
    const int b    = blockIdx.x;
    const int ustart = (b < NB14) ? 14*b : 14*NB14 + 13*(b - NB14);
    const int upb    = (b < NB14) ? 14 : 13;

    const int u0 = 2*w;                         // local units u0, u0+1
    int nu = upb - u0; nu = nu < 0 ? 0 : (nu > 2 ? 2 : nu);

    // ---- prologue: W_hh slice -> REGISTERS (fp32 global -> half2 regs) ----
    // wreg[r*32 + ck*4 + q]: row r (= local (unit,gate), unit-major), chunk ck,
    // covering k = ck*256 + lane*8 .. +8. Same values/k-map as the smem version.
    half2 wreg[192];
    #pragma unroll
    for (int r = 0; r < 6; ++r) {
        const int lu   = u0 + r/3;
        const int gate = r - 3*(r/3);
        const bool valid = (r < 3) || (nu == 2);
        const float* wrow = W_hh + (size_t)(gate*H + ustart + lu) * H;
        #pragma unroll
        for (int ck = 0; ck < 8; ++ck) {
            const int k0 = ck*256 + lane*8;
            float4 a = make_float4(0.f,0.f,0.f,0.f), c = a;
            if (valid) {
                a = *(const float4*)(wrow + k0);
                c = *(const float4*)(wrow + k0 + 4);
            }
            wreg[r*32 + ck*4 + 0] = __floats2half2_rn(a.x, a.y);
            wreg[r*32 + ck*4 + 1] = __floats2half2_rn(a.z, a.w);
            wreg[r*32 + ck*4 + 2] = __floats2half2_rn(c.x, c.y);
            wreg[r*32 + ck*4 + 3] = __floats2half2_rn(c.z, c.w);
        }
    }

    for (int j = tid; j < upb*3; j += THREADS) {
        int lu = j/3, gate = j - 3*lu;
        int grow = gate*H + ustart + lu;
        cu[j] = g_u[grow]; cv[j] = g_v[grow]; ccs[j] = g_c[grow];
    }
    for (int j = tid; j < upb; j += THREADS) bhn[j] = b_hh[2*H + ustart + j];
    for (int k = tid; k < H; k += THREADS) wo_sm[k] = W_out[k];
    for (int k = tid; k < L; k += THREADS) {
        tp_sm[k]  = timepoints[k];
        pkd_sm[k] = pk_data[k];
        tf_sm[k]  = tf_mask[k];
    }
    const float bo = b_out[0];
    const float4* wo4 = (const float4*)wo_sm;
    __syncthreads();

    for (int t = 0; t < L-1; ++t) {
        // A: stage h_{t-1} (L1-bypass, MLP=3) and fold pred = wo.h from the
        //    SAME registers.
        const float4* hsrc = (const float4*)((t == 0) ? smiles : g_h[(t-1)&1]);
        float4* hd = (float4*)h_sm;
        const float4 v0 = __ldcg(hsrc + tid);
        const float4 v1 = __ldcg(hsrc + tid + 224);
        float4 v2 = make_float4(0.f, 0.f, 0.f, 0.f);
        if (tid < 64) v2 = __ldcg(hsrc + tid + 448);
        hd[tid]       = v0;
        hd[tid + 224] = v1;
        if (tid < 64) hd[tid + 448] = v2;
        {
            const float4 q0 = wo4[tid];
            const float4 q1 = wo4[tid + 224];
            float sp = q0.x*v0.x + q0.y*v0.y + q0.z*v0.z + q0.w*v0.w
                     + q1.x*v1.x + q1.y*v1.y + q1.z*v1.z + q1.w*v1.w;
            if (tid < 64) {
                const float4 q2 = wo4[tid + 448];
                sp += q2.x*v2.x + q2.y*v2.y + q2.z*v2.z + q2.w*v2.w;
            }
            #pragma unroll
            for (int o = 16; o; o >>= 1) sp += __shfl_xor_sync(0xffffffffu, sp, o);
            if (lane == 0) ppart[w] = sp;
        }
        __syncthreads();                                   // h_sm + ppart ready

        const float pred = ((ppart[0]+ppart[1])+(ppart[2]+ppart[3]))
                         + ((ppart[4]+ppart[5])+ppart[6]) + bo;  // identical everywhere
        if (b == 0 && tid == 0 && t > 0) out[t] = pred;
        const float pk = (t > 0 && tf_sm[t] == 1) ? pred : pkd_sm[t];
        const float tp = tp_sm[t];

        // C: 6 dot products — weights from REGISTERS, h from smem, fp32 acc.
        float acc[6] = {0.f,0.f,0.f,0.f,0.f,0.f};
        #pragma unroll
        for (int ck = 0; ck < 8; ++ck) {
            const int k0 = ck*256 + lane*8;
            const float4 ha = *(const float4*)(h_sm + k0);
            const float4 hb = *(const float4*)(h_sm + k0 + 4);
            #pragma unroll
            for (int r = 0; r < 6; ++r) {
                const float2 f0 = __half22float2(wreg[r*32 + ck*4 + 0]);
                const float2 f1 = __half22float2(wreg[r*32 + ck*4 + 1]);
                const float2 f2 = __half22float2(wreg[r*32 + ck*4 + 2]);
                const float2 f3 = __half22float2(wreg[r*32 + ck*4 + 3]);
                acc[r] = fmaf(f0.x, ha.x, acc[r]); acc[r] = fmaf(f0.y, ha.y, acc[r]);
                acc[r] = fmaf(f1.x, ha.z, acc[r]); acc[r] = fmaf(f1.y, ha.w, acc[r]);
                acc[r] = fmaf(f2.x, hb.x, acc[r]); acc[r] = fmaf(f2.y, hb.y, acc[r]);
                acc[r] = fmaf(f3.x, hb.z, acc[r]); acc[r] = fmaf(f3.y, hb.w, acc[r]);
            }
        }
        // butterfly: every lane ends with all 6 full sums (enables split gates)
        #pragma unroll
        for (int o = 16; o; o >>= 1) {
            #pragma unroll
            for (int r = 0; r < 6; ++r)
                acc[r] += __shfl_xor_sync(0xffffffffu, acc[r], o);
        }

        // D: gate math split across lane0 (unit u0) and lane16 (unit u0+1)
        if ((lane == 0) || (lane == 16 && nu == 2)) {
            const int un = (lane == 0) ? 0 : 1;
            const int j = u0 + un, cb = j*3;
            const float dr = acc[un*3], dz = acc[un*3+1], dn = acc[un*3+2];
            const float ar = fmaf(pk, cu[cb],   fmaf(tp, cv[cb],   ccs[cb]))   + dr;
            const float az = fmaf(pk, cu[cb+1], fmaf(tp, cv[cb+1], ccs[cb+1])) + dz;
            const float r  = 1.f/(1.f + __expf(-ar));
            const float z  = 1.f/(1.f + __expf(-az));
            const float an = fmaf(pk, cu[cb+2], fmaf(tp, cv[cb+2], ccs[cb+2]))
                           + r*(dn + bhn[j]);
            const float n  = tanhf(an);
            const float hnew = fmaf(1.f - z, n, z * h_sm[ustart + j]);
            g_h[t&1][ustart + j] = hnew;
        }
        __syncthreads();                                   // all h stores issued

        // E: minimal grid barrier (R1/R6/R10-proven pattern — frozen)
        if (tid == 0) {
            __threadfence();                               // release h stores
            atomicAdd(&g_bar, 1u);                         // RED (result unused)
            const unsigned target = (unsigned)GRID * (unsigned)(t+1);
            volatile unsigned* vb = &g_bar;
            while (*vb < target) { }
            __threadfence();                               // acquire others' h
        }
        __syncthreads();
    }

    // epilogue: out[255] = W_out . h_final + bo  (block 0 only)
    if (b == 0) {
        const float4* hsrc = (const float4*)g_h[(L-2)&1];
        float4* hd = (float4*)h_sm;
        for (int i = tid; i < H/4; i += THREADS) hd[i] = __ldcg(hsrc + i);
        __syncthreads();
        float s = 0.f;
        for (int k = tid; k < H; k += THREADS) s = fmaf(wo_sm[k], h_sm[k], s);
        #pragma unroll
        for (int o = 16; o; o >>= 1) s += __shfl_xor_sync(0xffffffffu, s, o);
        if (lane == 0) ppart[w] = s;
        __syncthreads();
        if (tid == 0)
            out[L-1] = ((ppart[0]+ppart[1])+(ppart[2]+ppart[3]))
                     + ((ppart[4]+ppart[5])+ppart[6]) + bo;
    }
}

// ---------------------------------------------------------------------------
// Inputs: 0 timepoints, 1 pk_data, 2 input_len, 3 emb_patient, 4 drug_route,
// 5 dose, 6 smiles, 7 tf_mask, 8 emb_table, 9 W_pre, 10 b_pre, 11 W_ih,
// 12 W_hh, 13 b_ih, 14 b_hh, 15 W_out, 16 b_out
// ---------------------------------------------------------------------------
extern "C" void kernel_launch(void* const* d_in, const int* in_sizes, int n_in,
                              void* d_out, int out_size)
{
    const float* timepoints = (const float*)d_in[0];
    const float* pk_data    = (const float*)d_in[1];
    const int*   pat        = (const int*)  d_in[3];
    const float* route      = (const float*)d_in[4];
    const float* dose       = (const float*)d_in[5];
    const float* smiles     = (const float*)d_in[6];
    const int*   tf_mask    = (const int*)  d_in[7];
    const float* emb_table  = (const float*)d_in[8];
    const float* W_pre      = (const float*)d_in[9];
    const float* b_pre      = (const float*)d_in[10];
    const float* W_ih       = (const float*)d_in[11];
    const float* W_hh       = (const float*)d_in[12];
    const float* b_ih       = (const float*)d_in[13];
    const float* b_hh       = (const float*)d_in[14];
    const float* W_out      = (const float*)d_in[15];
    const float* b_out      = (const float*)d_in[16];
    float* out = (float*)d_out;

    prep_fused<<<G3/8, 256>>>(W_pre, b_pre, dose, route, pat, emb_table,
                              W_ih, b_ih, b_hh, pk_data, out);
    gru_kernel<<<GRID, THREADS>>>(W_hh, b_hh, W_out, b_out, smiles,
                                  pk_data, timepoints, tf_mask, out);
}